// round 15
// baseline (speedup 1.0000x reference)
#include <cuda_runtime.h>
#include <math.h>

#define B 4
#define N0 4096
#define STEPS 10
#define KNN 64
#define NEWP 1152
#define GDIM 256
#define HDIM 128
#define NMAX (N0 + STEPS*NEWP)   // 15616
#define NEWT (STEPS*NEWP)        // 11520
#define REF_OUT (NEWP*3)         // 3456

// ---------------- scratch (static device globals; no runtime alloc) ----------------
__device__ float    g_canvas[B * NMAX * 3];
__device__ float    g_scores[B * NMAX];
__device__ float    g_base[B * 128];
__device__ float    g_h[B * HDIM];
__device__ float    g_c[B * HDIM];
__device__ unsigned g_gmax[B * GDIM];   // running max of f3 (ordered-uint keys)
__device__ unsigned g_smax[B];          // per-step score max (keys)
__device__ int      g_encCnt[B];        // last-block counters for k_enc tail
__device__ int      g_chCnt;            // last-block counter for chamfer tail
__device__ float    g_closs[4];

// ordered-uint key for float (monotone for unsigned compare)
__device__ __forceinline__ unsigned fkey(float f) {
    unsigned u = __float_as_uint(f);
    return (u & 0x80000000u) ? ~u : (u | 0x80000000u);
}
__device__ __forceinline__ float fdec(unsigned k) {
    unsigned u = (k & 0x80000000u) ? (k & 0x7fffffffu) : ~k;
    return __uint_as_float(u);
}
__device__ __forceinline__ float sigm(float x) { return 1.f / (1.f + expf(-x)); }

// ---------------- init ----------------
__global__ void k_init(const float* __restrict__ points) {
    int i = blockIdx.x * 256 + threadIdx.x;
    if (i < B * N0 * 3) {
        int b = i / (N0 * 3);
        int r = i - b * (N0 * 3);
        g_canvas[b * NMAX * 3 + r] = points[i];
    }
    if (i < B * HDIM) { g_h[i] = 0.f; g_c[i] = 0.f; }
    if (i < B * GDIM) g_gmax[i] = 0u;            // key 0 < key(any real float)
    if (i < B) { g_smax[i] = 0u; g_encCnt[i] = 0; }
    if (i == 0) g_chCnt = 0;
    if (i < 4) g_closs[i] = 0.f;
}

// ---------------- fused encoder: layers 1+2+3 + running channel max + attbase tail ----------------
__global__ __launch_bounds__(256) void k_enc(
    const float* __restrict__ w1, const float* __restrict__ b1,
    const float* __restrict__ w2, const float* __restrict__ b2,
    const float* __restrict__ w3, const float* __restrict__ b3,
    const float* __restrict__ att_w1, const float* __restrict__ att_b1,
    int encFrom)
{
    int b = blockIdx.y;
    int tile0 = blockIdx.x * 32;
    int tid = threadIdx.x;
    __shared__ float w1s[192], b1s[64];
    __shared__ float xs[32][3];
    __shared__ float f1s[32 * 64];
    __shared__ float f2s[32 * 128];
    __shared__ int isLast;

    if (tid < 64) b1s[tid] = b1[tid];
    if (tid < 192) w1s[tid] = w1[tid];
    if (tid < 96) {
        int p = tid / 3, d = tid - p * 3;
        xs[p][d] = g_canvas[(b * NMAX + encFrom + tile0 + p) * 3 + d];
    }
    int jj = tid & 127;        // layer-2 output channel
    int half = tid >> 7;       // which 16-point half
    float w2c[64];
#pragma unroll
    for (int k = 0; k < 64; ++k) w2c[k] = w2[k * 128 + jj];
    float bias2 = b2[jj];
    __syncthreads();

    // layer 1: 32 pts x 64 ch
#pragma unroll
    for (int t = 0; t < 8; ++t) {
        int id = t * 256 + tid;
        int p = id >> 6, j1 = id & 63;
        float v = b1s[j1] + xs[p][0] * w1s[j1] + xs[p][1] * w1s[64 + j1] + xs[p][2] * w1s[128 + j1];
        f1s[p * 64 + j1] = fmaxf(v, 0.f);
    }
    __syncthreads();

    // layer 2
    const float4* f1s4 = reinterpret_cast<const float4*>(f1s);
#pragma unroll 1
    for (int pp = 0; pp < 16; ++pp) {
        int p = half * 16 + pp;
        float acc = bias2;
#pragma unroll
        for (int k4 = 0; k4 < 16; ++k4) {
            float4 v = f1s4[p * 16 + k4];
            acc += v.x * w2c[4 * k4] + v.y * w2c[4 * k4 + 1] + v.z * w2c[4 * k4 + 2] + v.w * w2c[4 * k4 + 3];
        }
        f2s[p * 128 + jj] = fmaxf(acc, 0.f);
    }
    __syncthreads();

    // layer 3 + tile max
    float w3c[128];
#pragma unroll
    for (int k = 0; k < 128; ++k) w3c[k] = w3[k * 256 + tid];
    float bias = b3[tid];
    const float4* f2s4 = reinterpret_cast<const float4*>(f2s);
    float vmax = -3.4e38f;
#pragma unroll 1
    for (int p = 0; p < 32; p += 2) {
        float a0 = bias, a1 = bias;
#pragma unroll
        for (int k4 = 0; k4 < 32; ++k4) {
            float4 v0 = f2s4[p * 32 + k4];
            float4 v1 = f2s4[p * 32 + 32 + k4];
            a0 += v0.x * w3c[4 * k4] + v0.y * w3c[4 * k4 + 1] + v0.z * w3c[4 * k4 + 2] + v0.w * w3c[4 * k4 + 3];
            a1 += v1.x * w3c[4 * k4] + v1.y * w3c[4 * k4 + 1] + v1.z * w3c[4 * k4 + 2] + v1.w * w3c[4 * k4 + 3];
        }
        vmax = fmaxf(vmax, fmaxf(a0, a1));
    }
    atomicMax(&g_gmax[b * GDIM + tid], fkey(vmax));

    // ---- last-block-per-batch tail: attention base for this batch ----
    __threadfence();
    __syncthreads();
    if (tid == 0) {
        int c = atomicAdd(&g_encCnt[b], 1);
        isLast = (c == (int)gridDim.x - 1);
        if (isLast) g_encCnt[b] = 0;   // reset for next step
    }
    __syncthreads();
    if (!isLast) return;

    // reuse f1s as gf[256] + hs[128] staging
    float* gf = f1s;            // 256 floats
    float* hs = f1s + 256;      // 128 floats
    if (tid < 256) gf[tid] = fdec(g_gmax[b * GDIM + tid]);
    if (tid < 128) hs[tid] = g_h[b * HDIM + tid];
    __syncthreads();
    if (tid < 128) {
        int j = tid;
        float a0 = att_b1[j], a1 = 0.f, a2 = 0.f, a3 = 0.f;
#pragma unroll 4
        for (int i = 0; i < GDIM; i += 4) {
            a0 += gf[i]     * att_w1[(3 + i) * 128 + j];
            a1 += gf[i + 1] * att_w1[(4 + i) * 128 + j];
            a2 += gf[i + 2] * att_w1[(5 + i) * 128 + j];
            a3 += gf[i + 3] * att_w1[(6 + i) * 128 + j];
        }
#pragma unroll 4
        for (int i = 0; i < HDIM; i += 4) {
            a0 += hs[i]     * att_w1[(259 + i) * 128 + j];
            a1 += hs[i + 1] * att_w1[(260 + i) * 128 + j];
            a2 += hs[i + 2] * att_w1[(261 + i) * 128 + j];
            a3 += hs[i + 3] * att_w1[(262 + i) * 128 + j];
        }
        g_base[b * 128 + j] = (a0 + a1) + (a2 + a3);
    }
}

// ---------------- attention scores + global max ----------------
__global__ __launch_bounds__(128) void k_scores(
    const float* __restrict__ att_w1, const float* __restrict__ att_w2,
    const float* __restrict__ att_b2, int N)
{
    int b = blockIdx.y;
    int tid = threadIdx.x;
    int n = blockIdx.x * 128 + tid;
    __shared__ float4 pk[128];
    __shared__ float w2s[128];
    pk[tid] = make_float4(g_base[b * 128 + tid], att_w1[tid], att_w1[128 + tid], att_w1[256 + tid]);
    w2s[tid] = att_w2[tid];
    __syncthreads();
    float s = -3.4e38f;
    if (n < N) {
        const float* cp = g_canvas + (b * NMAX + n) * 3;
        float x = cp[0], y = cp[1], z = cp[2];
        float c0 = att_b2[0], c1 = 0.f, c2 = 0.f, c3 = 0.f;
#pragma unroll 4
        for (int j = 0; j < 128; j += 4) {
            float4 q0 = pk[j], q1 = pk[j + 1], q2 = pk[j + 2], q3 = pk[j + 3];
            c0 += fmaxf(q0.x + x * q0.y + y * q0.z + z * q0.w, 0.f) * w2s[j];
            c1 += fmaxf(q1.x + x * q1.y + y * q1.z + z * q1.w, 0.f) * w2s[j + 1];
            c2 += fmaxf(q2.x + x * q2.y + y * q2.z + z * q2.w, 0.f) * w2s[j + 2];
            c3 += fmaxf(q3.x + x * q3.y + y * q3.z + z * q3.w, 0.f) * w2s[j + 3];
        }
        float acc = (c0 + c1) + (c2 + c3);
        g_scores[b * NMAX + n] = acc;
        s = acc;
    }
    float v = s;
#pragma unroll
    for (int o = 16; o; o >>= 1) v = fmaxf(v, __shfl_down_sync(0xffffffffu, v, o));
    __shared__ float wmax[4];
    if ((tid & 31) == 0) wmax[tid >> 5] = v;
    __syncthreads();
    if (tid == 0) {
        float m = fmaxf(fmaxf(wmax[0], wmax[1]), fmaxf(wmax[2], wmax[3]));
        atomicMax(&g_smax[b], fkey(m));
    }
}

// ---------------- fused step tail: softmax sums -> center -> exact top-K -> LSTM -> refine ----------------
// Exact jax top_k semantics. Radix-4 binary searches (greedy max-T over a monotone
// lattice is radix-invariant -> identical T/Tidx to bit-by-bit): d2 search 15 pair-rounds
// + 1 single-bit round; tie-break index search 7 pair-rounds. One barrier per round via
// pre-zeroed per-round shared counters.
__global__ __launch_bounds__(1024) void k_step(
    const float* __restrict__ wih, const float* __restrict__ whh,
    const float* __restrict__ bih, const float* __restrict__ bhh,
    const float* __restrict__ rw1, const float* __restrict__ rb1,
    const float* __restrict__ rw2, const float* __restrict__ rb2,
    int N)
{
    __shared__ float fred[32][4];
    __shared__ unsigned cnt[72];   // [0..44] d2 pairs, [45] d2 bit0, [46] strict-less, [47..67] idx pairs
    __shared__ float cs[3];
    __shared__ float acc3[3];
    __shared__ float in_s[262];
    __shared__ float gsm[512];
    __shared__ float hnew[128];
    __shared__ float hid[128];

    int b = blockIdx.x, tid = threadIdx.x;
    int wid = tid >> 5, lane = tid & 31;
    float smax = fdec(g_smax[b]);
    if (tid < 72) cnt[tid] = 0u;

    // --- Phase A: softmax partial sums (e, e*x, e*y, e*z) ---
    float e = 0.f, ex = 0.f, ey = 0.f, ez = 0.f;
#pragma unroll 4
    for (int t = 0; t < 16; ++t) {
        int n = t * 1024 + tid;
        if (n < N) {
            const float* cp = g_canvas + (b * NMAX + n) * 3;
            float q = expf(g_scores[b * NMAX + n] - smax);
            e += q; ex += q * cp[0]; ey += q * cp[1]; ez += q * cp[2];
        }
    }
#pragma unroll
    for (int o = 16; o; o >>= 1) {
        e  += __shfl_down_sync(0xffffffffu, e, o);
        ex += __shfl_down_sync(0xffffffffu, ex, o);
        ey += __shfl_down_sync(0xffffffffu, ey, o);
        ez += __shfl_down_sync(0xffffffffu, ez, o);
    }
    if (lane == 0) { fred[wid][0] = e; fred[wid][1] = ex; fred[wid][2] = ey; fred[wid][3] = ez; }
    __syncthreads();
    if (tid == 0) {
        float s0 = 0.f, s1 = 0.f, s2 = 0.f, s3 = 0.f;
#pragma unroll
        for (int w = 0; w < 32; ++w) { s0 += fred[w][0]; s1 += fred[w][1]; s2 += fred[w][2]; s3 += fred[w][3]; }
        float inv = 1.f / s0;
        cs[0] = s1 * inv; cs[1] = s2 * inv; cs[2] = s3 * inv;
    }
    __syncthreads();
    float cx = cs[0], cy = cs[1], cz = cs[2];

    // --- Phase B: distances into registers ---
    unsigned kreg[16];
#pragma unroll
    for (int t = 0; t < 16; ++t) {
        int n = t * 1024 + tid;
        if (n < N) {
            const float* cp = g_canvas + (b * NMAX + n) * 3;
            float dx = cp[0] - cx, dy = cp[1] - cy, dz = cp[2] - cz;
            kreg[t] = __float_as_uint(dx * dx + dy * dy + dz * dz);
        } else {
            kreg[t] = 0xFFFFFFFFu;   // never < any test threshold, never == T
        }
    }

    // --- Phase C: radix-4 search for K-th smallest d2 key ---
    // invariant: count(key < T) < KNN; keys are nonneg fp32 bits (bit31=0, bits 30..0)
    unsigned T = 0;
    {
        int r = 0;
#pragma unroll 1
        for (int bpos = 29; bpos >= 1; bpos -= 2, ++r) {   // pair (bpos+1, bpos): 15 rounds
            unsigned t1 = T + (1u << bpos), t2 = T + (2u << bpos), t3 = T + (3u << bpos);
            unsigned c1 = 0, c2 = 0, c3 = 0;
#pragma unroll
            for (int t = 0; t < 16; ++t) {
                c1 += (kreg[t] < t1) ? 1u : 0u;
                c2 += (kreg[t] < t2) ? 1u : 0u;
                c3 += (kreg[t] < t3) ? 1u : 0u;
            }
            c1 = __reduce_add_sync(0xffffffffu, c1);
            c2 = __reduce_add_sync(0xffffffffu, c2);
            c3 = __reduce_add_sync(0xffffffffu, c3);
            if (lane == 0) {
                if (c1) atomicAdd(&cnt[r * 3 + 0], c1);
                if (c2) atomicAdd(&cnt[r * 3 + 1], c2);
                if (c3) atomicAdd(&cnt[r * 3 + 2], c3);
            }
            __syncthreads();
            if (cnt[r * 3 + 2] < KNN)      T = t3;
            else if (cnt[r * 3 + 1] < KNN) T = t2;
            else if (cnt[r * 3 + 0] < KNN) T = t1;
        }
        // final single bit 0
        {
            unsigned t1 = T + 1u;
            unsigned c1 = 0;
#pragma unroll
            for (int t = 0; t < 16; ++t) c1 += (kreg[t] < t1) ? 1u : 0u;
            c1 = __reduce_add_sync(0xffffffffu, c1);
            if (lane == 0 && c1) atomicAdd(&cnt[45], c1);
            __syncthreads();
            if (cnt[45] < KNN) T = t1;
        }
    }
    // strict-less count
    {
        unsigned c = 0;
#pragma unroll
        for (int t = 0; t < 16; ++t) c += (kreg[t] < T) ? 1u : 0u;
        c = __reduce_add_sync(0xffffffffu, c);
        if (lane == 0 && c) atomicAdd(&cnt[46], c);
        __syncthreads();
    }
    int need = KNN - (int)cnt[46];

    // --- Phase D1: strict-less patch sums (parallel) ---
    {
        float sx = 0.f, sy = 0.f, sz = 0.f;
#pragma unroll
        for (int t = 0; t < 16; ++t) {
            int n = t * 1024 + tid;
            if (n < N && kreg[t] < T) {
                const float* cp = g_canvas + (b * NMAX + n) * 3;
                sx += cp[0]; sy += cp[1]; sz += cp[2];
            }
        }
#pragma unroll
        for (int o = 16; o; o >>= 1) {
            sx += __shfl_down_sync(0xffffffffu, sx, o);
            sy += __shfl_down_sync(0xffffffffu, sy, o);
            sz += __shfl_down_sync(0xffffffffu, sz, o);
        }
        if (lane == 0) { fred[wid][0] = sx; fred[wid][1] = sy; fred[wid][2] = sz; }
        __syncthreads();
        if (tid == 0) {
            float tx = 0.f, ty = 0.f, tz = 0.f;
#pragma unroll
            for (int w = 0; w < 32; ++w) { tx += fred[w][0]; ty += fred[w][1]; tz += fred[w][2]; }
            acc3[0] = tx; acc3[1] = ty; acc3[2] = tz;
        }
        __syncthreads();
    }

    // --- Phase D2: radix-4 tie-break — need-th smallest tied index (exact; indices unique) ---
    if (need > 0) {
        unsigned Tidx = 0;
        int r = 0;
#pragma unroll 1
        for (int bpos = 12; bpos >= 0; bpos -= 2, ++r) {   // pairs (13,12)...(1,0): 7 rounds
            unsigned t1 = Tidx + (1u << bpos), t2 = Tidx + (2u << bpos), t3 = Tidx + (3u << bpos);
            unsigned c1 = 0, c2 = 0, c3 = 0;
#pragma unroll
            for (int t = 0; t < 16; ++t) {
                unsigned n = (unsigned)(t * 1024 + tid);
                bool tied = (kreg[t] == T);
                c1 += (tied && n < t1) ? 1u : 0u;
                c2 += (tied && n < t2) ? 1u : 0u;
                c3 += (tied && n < t3) ? 1u : 0u;
            }
            c1 = __reduce_add_sync(0xffffffffu, c1);
            c2 = __reduce_add_sync(0xffffffffu, c2);
            c3 = __reduce_add_sync(0xffffffffu, c3);
            if (lane == 0) {
                if (c1) atomicAdd(&cnt[47 + r * 3 + 0], c1);
                if (c2) atomicAdd(&cnt[47 + r * 3 + 1], c2);
                if (c3) atomicAdd(&cnt[47 + r * 3 + 2], c3);
            }
            __syncthreads();
            if (cnt[47 + r * 3 + 2] < (unsigned)need)      Tidx = t3;
            else if (cnt[47 + r * 3 + 1] < (unsigned)need) Tidx = t2;
            else if (cnt[47 + r * 3 + 0] < (unsigned)need) Tidx = t1;
        }
        // include tied with n <= Tidx (exactly `need` lowest-index tied points)
        float sx = 0.f, sy = 0.f, sz = 0.f;
#pragma unroll
        for (int t = 0; t < 16; ++t) {
            unsigned n = (unsigned)(t * 1024 + tid);
            if (kreg[t] == T && n <= Tidx) {
                const float* cp = g_canvas + (b * NMAX + (int)n) * 3;
                sx += cp[0]; sy += cp[1]; sz += cp[2];
            }
        }
#pragma unroll
        for (int o = 16; o; o >>= 1) {
            sx += __shfl_down_sync(0xffffffffu, sx, o);
            sy += __shfl_down_sync(0xffffffffu, sy, o);
            sz += __shfl_down_sync(0xffffffffu, sz, o);
        }
        if (lane == 0) { fred[wid][0] = sx; fred[wid][1] = sy; fred[wid][2] = sz; }
        __syncthreads();
        if (tid == 0) {
            float tx = acc3[0], ty = acc3[1], tz = acc3[2];
#pragma unroll
            for (int w = 0; w < 32; ++w) { tx += fred[w][0]; ty += fred[w][1]; tz += fred[w][2]; }
            acc3[0] = tx; acc3[1] = ty; acc3[2] = tz;
        }
        __syncthreads();
    }

    if (tid == 0) {
        in_s[256] = cx; in_s[257] = cy; in_s[258] = cz;
        in_s[259] = acc3[0] * (1.f / KNN) - cx;
        in_s[260] = acc3[1] * (1.f / KNN) - cy;
        in_s[261] = acc3[2] * (1.f / KNN) - cz;
        g_smax[b] = 0u;   // reset for next step
    }
    if (tid < 256) in_s[tid] = fdec(g_gmax[b * GDIM + tid]);
    if (tid < 128) hnew[tid] = g_h[b * HDIM + tid];   // old h staged
    __syncthreads();

    // --- Phase E: LSTM gates (512 threads) ---
    if (tid < 512) {
        int j = tid;
        float a0 = bih[j] + bhh[j], a1 = 0.f;
#pragma unroll 2
        for (int i = 0; i < 262; i += 2) {
            a0 += in_s[i] * wih[i * 512 + j];
            if (i + 1 < 262) a1 += in_s[i + 1] * wih[(i + 1) * 512 + j];
        }
#pragma unroll 2
        for (int i = 0; i < 128; i += 2) {
            a0 += hnew[i]     * whh[i * 512 + j];
            a1 += hnew[i + 1] * whh[(i + 1) * 512 + j];
        }
        gsm[j] = a0 + a1;
    }
    __syncthreads();
    if (tid < 128) {
        float gi = gsm[tid], gf = gsm[128 + tid], gg = gsm[256 + tid], go = gsm[384 + tid];
        float cn = sigm(gf) * g_c[b * HDIM + tid] + sigm(gi) * tanhf(gg);
        g_c[b * HDIM + tid] = cn;
        float hv = sigm(go) * tanhf(cn);
        g_h[b * HDIM + tid] = hv;
        hid[tid] = hv;
    }
    __syncthreads();
    // --- Phase F: refine layer 1 ---
    if (tid < 128) {
        float a = rb1[tid];
#pragma unroll 4
        for (int k = 0; k < 128; ++k) a += hid[k] * rw1[k * 128 + tid];
        hnew[tid] = fmaxf(a, 0.f);   // reuse hnew as hidden
    }
    __syncthreads();
    // --- Phase G: refine layer 2, append 1152 points ---
    for (int o = tid; o < REF_OUT; o += 1024) {
        float a = rb2[o];
#pragma unroll 4
        for (int k = 0; k < 128; ++k) a += hnew[k] * rw2[k * REF_OUT + o];
        int p = o / 3, d = o - p * 3;
        float ctr = (d == 0) ? cx : (d == 1) ? cy : cz;
        g_canvas[(b * NMAX + N + p) * 3 + d] = a * 0.02f + ctr;
    }
}

// ---------------- chamfer: 4 directions in one launch + fused final reduction ----------------
__global__ __launch_bounds__(256) void k_chamfer(const float* __restrict__ gt, float* __restrict__ out)
{
    int slot = blockIdx.z;
    int b = blockIdx.y;
    int tid = threadIdx.x;
    int totalBlocks = gridDim.x * gridDim.y * gridDim.z;
    __shared__ int chLast;

    const float* canvas_b = g_canvas + (size_t)b * NMAX * 3;
    const float* gt_b = gt + (size_t)b * N0 * 3;
    const float* X; const float* Y; int Nx, Ny;
    if (slot == 0)      { X = canvas_b;            Y = gt_b;              Nx = N0;   Ny = N0;   }
    else if (slot == 1) { X = gt_b;                Y = canvas_b;          Nx = N0;   Ny = N0;   }
    else if (slot == 2) { X = canvas_b + N0 * 3;   Y = gt_b;              Nx = NEWT; Ny = N0;   }
    else                { X = gt_b;                Y = canvas_b + N0 * 3; Nx = N0;   Ny = NEWT; }

    bool doWork = (blockIdx.x * 512 < Nx);
    if (doWork) {
        int i0 = blockIdx.x * 512 + tid;
        int i1 = i0 + 256;

        __shared__ float4 ys[256];

        bool v0 = i0 < Nx, v1 = i1 < Nx;
        float a0 = 0.f, a1 = 0.f, a2 = 0.f;
        float b0 = 0.f, b1v = 0.f, b2v = 0.f;
        if (v0) { const float* xp = X + (size_t)i0 * 3; a0 = xp[0]; a1 = xp[1]; a2 = xp[2]; }
        if (v1) { const float* xp = X + (size_t)i1 * 3; b0 = xp[0]; b1v = xp[1]; b2v = xp[2]; }

        float amin0 = 3.4e38f, amin1 = 3.4e38f;
        float bmin0 = 3.4e38f, bmin1 = 3.4e38f;
        for (int m0 = 0; m0 < Ny; m0 += 256) {      // Ny always multiple of 256
            __syncthreads();
            {
                const float* yp = Y + (size_t)(m0 + tid) * 3;
                float y0 = yp[0], y1 = yp[1], y2 = yp[2];
                ys[tid] = make_float4(-2.f * y0, -2.f * y1, -2.f * y2, y0 * y0 + y1 * y1 + y2 * y2);
            }
            __syncthreads();
#pragma unroll 4
            for (int t = 0; t < 256; t += 2) {
                float4 q0 = ys[t];
                float4 q1 = ys[t + 1];
                float da0 = q0.w + a0 * q0.x + a1 * q0.y + a2 * q0.z;
                float da1 = q1.w + a0 * q1.x + a1 * q1.y + a2 * q1.z;
                float db0 = q0.w + b0 * q0.x + b1v * q0.y + b2v * q0.z;
                float db1 = q1.w + b0 * q1.x + b1v * q1.y + b2v * q1.z;
                amin0 = fminf(amin0, da0);
                amin1 = fminf(amin1, da1);
                bmin0 = fminf(bmin0, db0);
                bmin1 = fminf(bmin1, db1);
            }
        }
        float ra = v0 ? (fminf(amin0, amin1) + a0 * a0 + a1 * a1 + a2 * a2) : 0.f;
        float rb = v1 ? (fminf(bmin0, bmin1) + b0 * b0 + b1v * b1v + b2v * b2v) : 0.f;

        float v = ra + rb;
#pragma unroll
        for (int o = 16; o; o >>= 1) v += __shfl_down_sync(0xffffffffu, v, o);
        __shared__ float wsum[8];
        if ((tid & 31) == 0) wsum[tid >> 5] = v;
        __syncthreads();
        if (tid == 0) {
            float s = 0.f;
#pragma unroll
            for (int w = 0; w < 8; ++w) s += wsum[w];
            atomicAdd(&g_closs[slot], s);
        }
    }

    // ---- fused final reduction: last block computes the loss ----
    __threadfence();
    __syncthreads();
    if (tid == 0) {
        int c = atomicAdd(&g_chCnt, 1);
        chLast = (c == totalBlocks - 1);
    }
    __syncthreads();
    if (chLast && tid == 0) {
        out[0] = 0.1f * (g_closs[0] * (1.f / (B * (float)N0)) + g_closs[1] * (1.f / (B * (float)N0)))
               + (g_closs[2] * (1.f / (B * (float)NEWT)) + g_closs[3] * (1.f / (B * (float)N0)));
        g_closs[0] = 0.f; g_closs[1] = 0.f; g_closs[2] = 0.f; g_closs[3] = 0.f;
        g_chCnt = 0;
    }
}

// ---------------- host ----------------
extern "C" void kernel_launch(void* const* d_in, const int* in_sizes, int n_in,
                              void* d_out, int out_size)
{
    const float* points   = (const float*)d_in[0];
    const float* gt       = (const float*)d_in[1];
    const float* enc_w1   = (const float*)d_in[2];
    const float* enc_b1   = (const float*)d_in[3];
    const float* enc_w2   = (const float*)d_in[4];
    const float* enc_b2   = (const float*)d_in[5];
    const float* enc_w3   = (const float*)d_in[6];
    const float* enc_b3   = (const float*)d_in[7];
    const float* att_w1   = (const float*)d_in[8];
    const float* att_b1   = (const float*)d_in[9];
    const float* att_w2   = (const float*)d_in[10];
    const float* att_b2   = (const float*)d_in[11];
    const float* lstm_wih = (const float*)d_in[12];
    const float* lstm_whh = (const float*)d_in[13];
    const float* lstm_bih = (const float*)d_in[14];
    const float* lstm_bhh = (const float*)d_in[15];
    const float* ref_w1   = (const float*)d_in[16];
    const float* ref_b1   = (const float*)d_in[17];
    const float* ref_w2   = (const float*)d_in[18];
    const float* ref_b2   = (const float*)d_in[19];
    float* out = (float*)d_out;

    k_init<<<(B * N0 * 3 + 255) / 256, 256>>>(points);

    for (int s = 0; s < STEPS; ++s) {
        int N = N0 + s * NEWP;
        int encFrom = (s == 0) ? 0 : (N - NEWP);
        int nNew = N - encFrom;  // 4096 or 1152, both divisible by 32
        dim3 ge(nNew / 32, B);
        k_enc<<<ge, 256>>>(enc_w1, enc_b1, enc_w2, enc_b2, enc_w3, enc_b3,
                           att_w1, att_b1, encFrom);
        dim3 gs((N + 127) / 128, B);
        k_scores<<<gs, 128>>>(att_w1, att_w2, att_b2, N);
        k_step<<<B, 1024>>>(lstm_wih, lstm_whh, lstm_bih, lstm_bhh,
                            ref_w1, ref_b1, ref_w2, ref_b2, N);
    }

    dim3 gc((NEWT + 511) / 512, B, 4);   // 23 x 4 x 4; small slots skip work, still arrive
    k_chamfer<<<gc, 256>>>(gt, out);
}

// round 17
// speedup vs baseline: 1.2809x; 1.2809x over previous
#include <cuda_runtime.h>
#include <math.h>

#define B 4
#define N0 4096
#define STEPS 10
#define KNN 64
#define NEWP 1152
#define GDIM 256
#define HDIM 128
#define NMAX (N0 + STEPS*NEWP)   // 15616
#define NEWT (STEPS*NEWP)        // 11520
#define REF_OUT (NEWP*3)         // 3456

// ---------------- scratch (static device globals; no runtime alloc) ----------------
__device__ float    g_canvas[B * NMAX * 3];
__device__ float    g_scores[B * NMAX];
__device__ float    g_base[B * 128];
__device__ float    g_h[B * HDIM];
__device__ float    g_c[B * HDIM];
__device__ unsigned g_gmax[B * GDIM];   // running max of f3 (ordered-uint keys)
__device__ unsigned g_smax[B];          // per-step score max (keys)
__device__ int      g_encCnt[B];        // last-block counters for k_enc tail
__device__ int      g_chCnt;            // last-block counter for chamfer tail
__device__ float    g_closs[4];

// ordered-uint key for float (monotone for unsigned compare)
__device__ __forceinline__ unsigned fkey(float f) {
    unsigned u = __float_as_uint(f);
    return (u & 0x80000000u) ? ~u : (u | 0x80000000u);
}
__device__ __forceinline__ float fdec(unsigned k) {
    unsigned u = (k & 0x80000000u) ? (k & 0x7fffffffu) : ~k;
    return __uint_as_float(u);
}
__device__ __forceinline__ float sigm(float x) { return 1.f / (1.f + expf(-x)); }

// ---------------- init ----------------
__global__ void k_init(const float* __restrict__ points) {
    int i = blockIdx.x * 256 + threadIdx.x;
    if (i < B * N0 * 3) {
        int b = i / (N0 * 3);
        int r = i - b * (N0 * 3);
        g_canvas[b * NMAX * 3 + r] = points[i];
    }
    if (i < B * HDIM) { g_h[i] = 0.f; g_c[i] = 0.f; }
    if (i < B * GDIM) g_gmax[i] = 0u;            // key 0 < key(any real float)
    if (i < B) { g_smax[i] = 0u; g_encCnt[i] = 0; }
    if (i == 0) g_chCnt = 0;
    if (i < 4) g_closs[i] = 0.f;
}

// ---------------- fused encoder: layers 1+2+3 + running channel max + attbase tail ----------------
__global__ __launch_bounds__(256) void k_enc(
    const float* __restrict__ w1, const float* __restrict__ b1,
    const float* __restrict__ w2, const float* __restrict__ b2,
    const float* __restrict__ w3, const float* __restrict__ b3,
    const float* __restrict__ att_w1, const float* __restrict__ att_b1,
    int encFrom)
{
    int b = blockIdx.y;
    int tile0 = blockIdx.x * 32;
    int tid = threadIdx.x;
    __shared__ float w1s[192], b1s[64];
    __shared__ float xs[32][3];
    __shared__ float f1s[32 * 64];
    __shared__ float f2s[32 * 128];
    __shared__ int isLast;

    if (tid < 64) b1s[tid] = b1[tid];
    if (tid < 192) w1s[tid] = w1[tid];
    if (tid < 96) {
        int p = tid / 3, d = tid - p * 3;
        xs[p][d] = g_canvas[(b * NMAX + encFrom + tile0 + p) * 3 + d];
    }
    int jj = tid & 127;        // layer-2 output channel
    int half = tid >> 7;       // which 16-point half
    float w2c[64];
#pragma unroll
    for (int k = 0; k < 64; ++k) w2c[k] = w2[k * 128 + jj];
    float bias2 = b2[jj];
    __syncthreads();

    // layer 1
#pragma unroll
    for (int t = 0; t < 8; ++t) {
        int id = t * 256 + tid;
        int p = id >> 6, j1 = id & 63;
        float v = b1s[j1] + xs[p][0] * w1s[j1] + xs[p][1] * w1s[64 + j1] + xs[p][2] * w1s[128 + j1];
        f1s[p * 64 + j1] = fmaxf(v, 0.f);
    }
    __syncthreads();

    // layer 2
    const float4* f1s4 = reinterpret_cast<const float4*>(f1s);
#pragma unroll 1
    for (int pp = 0; pp < 16; ++pp) {
        int p = half * 16 + pp;
        float acc = bias2;
#pragma unroll
        for (int k4 = 0; k4 < 16; ++k4) {
            float4 v = f1s4[p * 16 + k4];
            acc += v.x * w2c[4 * k4] + v.y * w2c[4 * k4 + 1] + v.z * w2c[4 * k4 + 2] + v.w * w2c[4 * k4 + 3];
        }
        f2s[p * 128 + jj] = fmaxf(acc, 0.f);
    }
    __syncthreads();

    // layer 3 + tile max
    float w3c[128];
#pragma unroll
    for (int k = 0; k < 128; ++k) w3c[k] = w3[k * 256 + tid];
    float bias = b3[tid];
    const float4* f2s4 = reinterpret_cast<const float4*>(f2s);
    float vmax = -3.4e38f;
#pragma unroll 1
    for (int p = 0; p < 32; p += 2) {
        float a0 = bias, a1 = bias;
#pragma unroll
        for (int k4 = 0; k4 < 32; ++k4) {
            float4 v0 = f2s4[p * 32 + k4];
            float4 v1 = f2s4[p * 32 + 32 + k4];
            a0 += v0.x * w3c[4 * k4] + v0.y * w3c[4 * k4 + 1] + v0.z * w3c[4 * k4 + 2] + v0.w * w3c[4 * k4 + 3];
            a1 += v1.x * w3c[4 * k4] + v1.y * w3c[4 * k4 + 1] + v1.z * w3c[4 * k4 + 2] + v1.w * w3c[4 * k4 + 3];
        }
        vmax = fmaxf(vmax, fmaxf(a0, a1));
    }
    atomicMax(&g_gmax[b * GDIM + tid], fkey(vmax));

    // ---- last-block-per-batch tail: attention base ----
    __threadfence();
    __syncthreads();
    if (tid == 0) {
        int c = atomicAdd(&g_encCnt[b], 1);
        isLast = (c == (int)gridDim.x - 1);
        if (isLast) g_encCnt[b] = 0;
    }
    __syncthreads();
    if (!isLast) return;

    float* gf = f1s;            // 256 floats
    float* hs = f1s + 256;      // 128 floats
    if (tid < 256) gf[tid] = fdec(g_gmax[b * GDIM + tid]);
    if (tid < 128) hs[tid] = g_h[b * HDIM + tid];
    __syncthreads();
    if (tid < 128) {
        int j = tid;
        float a0 = att_b1[j], a1 = 0.f, a2 = 0.f, a3 = 0.f;
#pragma unroll 4
        for (int i = 0; i < GDIM; i += 4) {
            a0 += gf[i]     * att_w1[(3 + i) * 128 + j];
            a1 += gf[i + 1] * att_w1[(4 + i) * 128 + j];
            a2 += gf[i + 2] * att_w1[(5 + i) * 128 + j];
            a3 += gf[i + 3] * att_w1[(6 + i) * 128 + j];
        }
#pragma unroll 4
        for (int i = 0; i < HDIM; i += 4) {
            a0 += hs[i]     * att_w1[(259 + i) * 128 + j];
            a1 += hs[i + 1] * att_w1[(260 + i) * 128 + j];
            a2 += hs[i + 2] * att_w1[(261 + i) * 128 + j];
            a3 += hs[i + 3] * att_w1[(262 + i) * 128 + j];
        }
        g_base[b * 128 + j] = (a0 + a1) + (a2 + a3);
    }
}

// ---------------- attention scores + global max ----------------
__global__ __launch_bounds__(128) void k_scores(
    const float* __restrict__ att_w1, const float* __restrict__ att_w2,
    const float* __restrict__ att_b2, int N)
{
    int b = blockIdx.y;
    int tid = threadIdx.x;
    int n = blockIdx.x * 128 + tid;
    __shared__ float4 pk[128];
    __shared__ float w2s[128];
    pk[tid] = make_float4(g_base[b * 128 + tid], att_w1[tid], att_w1[128 + tid], att_w1[256 + tid]);
    w2s[tid] = att_w2[tid];
    __syncthreads();
    float s = -3.4e38f;
    if (n < N) {
        const float* cp = g_canvas + (b * NMAX + n) * 3;
        float x = cp[0], y = cp[1], z = cp[2];
        float c0 = att_b2[0], c1 = 0.f, c2 = 0.f, c3 = 0.f;
#pragma unroll 4
        for (int j = 0; j < 128; j += 4) {
            float4 q0 = pk[j], q1 = pk[j + 1], q2 = pk[j + 2], q3 = pk[j + 3];
            c0 += fmaxf(q0.x + x * q0.y + y * q0.z + z * q0.w, 0.f) * w2s[j];
            c1 += fmaxf(q1.x + x * q1.y + y * q1.z + z * q1.w, 0.f) * w2s[j + 1];
            c2 += fmaxf(q2.x + x * q2.y + y * q2.z + z * q2.w, 0.f) * w2s[j + 2];
            c3 += fmaxf(q3.x + x * q3.y + y * q3.z + z * q3.w, 0.f) * w2s[j + 3];
        }
        float acc = (c0 + c1) + (c2 + c3);
        g_scores[b * NMAX + n] = acc;
        s = acc;
    }
    float v = s;
#pragma unroll
    for (int o = 16; o; o >>= 1) v = fmaxf(v, __shfl_down_sync(0xffffffffu, v, o));
    __shared__ float wmax[4];
    if ((tid & 31) == 0) wmax[tid >> 5] = v;
    __syncthreads();
    if (tid == 0) {
        float m = fmaxf(fmaxf(wmax[0], wmax[1]), fmaxf(wmax[2], wmax[3]));
        atomicMax(&g_smax[b], fkey(m));
    }
}

// ---------------- fused step tail ----------------
// Exact jax top_k (radix-4 searches, exact lowest-index tie-break). GEMV phases
// (LSTM gates / refine) rewritten as group-parallel float4 loads with smem
// partial-sum reduction: all 1024 threads stream weights via coalesced LDG.128
// with high MLP instead of 4 blocks of scalar latency-bound loads.
__global__ __launch_bounds__(1024) void k_step(
    const float* __restrict__ wih, const float* __restrict__ whh,
    const float* __restrict__ bih, const float* __restrict__ bhh,
    const float* __restrict__ rw1, const float* __restrict__ rb1,
    const float* __restrict__ rw2, const float* __restrict__ rb2,
    int N)
{
    __shared__ float fred[32][4];
    __shared__ unsigned cnt[72];
    __shared__ float cs[3];
    __shared__ float acc3[3];
    __shared__ float in_s[262];
    __shared__ float gsm[512];
    __shared__ float hnew[128];
    __shared__ float hid[128];
    __shared__ float part[8 * 512];   // GEMV partial sums (16KB; reused by F)

    int b = blockIdx.x, tid = threadIdx.x;
    int wid = tid >> 5, lane = tid & 31;
    float smax = fdec(g_smax[b]);
    if (tid < 72) cnt[tid] = 0u;

    // --- Phase A: softmax partial sums ---
    float e = 0.f, ex = 0.f, ey = 0.f, ez = 0.f;
#pragma unroll 4
    for (int t = 0; t < 16; ++t) {
        int n = t * 1024 + tid;
        if (n < N) {
            const float* cp = g_canvas + (b * NMAX + n) * 3;
            float q = expf(g_scores[b * NMAX + n] - smax);
            e += q; ex += q * cp[0]; ey += q * cp[1]; ez += q * cp[2];
        }
    }
#pragma unroll
    for (int o = 16; o; o >>= 1) {
        e  += __shfl_down_sync(0xffffffffu, e, o);
        ex += __shfl_down_sync(0xffffffffu, ex, o);
        ey += __shfl_down_sync(0xffffffffu, ey, o);
        ez += __shfl_down_sync(0xffffffffu, ez, o);
    }
    if (lane == 0) { fred[wid][0] = e; fred[wid][1] = ex; fred[wid][2] = ey; fred[wid][3] = ez; }
    __syncthreads();
    if (tid == 0) {
        float s0 = 0.f, s1 = 0.f, s2 = 0.f, s3 = 0.f;
#pragma unroll
        for (int w = 0; w < 32; ++w) { s0 += fred[w][0]; s1 += fred[w][1]; s2 += fred[w][2]; s3 += fred[w][3]; }
        float inv = 1.f / s0;
        cs[0] = s1 * inv; cs[1] = s2 * inv; cs[2] = s3 * inv;
    }
    __syncthreads();
    float cx = cs[0], cy = cs[1], cz = cs[2];

    // --- Phase B: distances into registers ---
    unsigned kreg[16];
#pragma unroll
    for (int t = 0; t < 16; ++t) {
        int n = t * 1024 + tid;
        if (n < N) {
            const float* cp = g_canvas + (b * NMAX + n) * 3;
            float dx = cp[0] - cx, dy = cp[1] - cy, dz = cp[2] - cz;
            kreg[t] = __float_as_uint(dx * dx + dy * dy + dz * dz);
        } else {
            kreg[t] = 0xFFFFFFFFu;
        }
    }

    // --- Phase C: radix-4 search for K-th smallest d2 key ---
    unsigned T = 0;
    {
        int r = 0;
#pragma unroll 1
        for (int bpos = 29; bpos >= 1; bpos -= 2, ++r) {
            unsigned t1 = T + (1u << bpos), t2 = T + (2u << bpos), t3 = T + (3u << bpos);
            unsigned c1 = 0, c2 = 0, c3 = 0;
#pragma unroll
            for (int t = 0; t < 16; ++t) {
                c1 += (kreg[t] < t1) ? 1u : 0u;
                c2 += (kreg[t] < t2) ? 1u : 0u;
                c3 += (kreg[t] < t3) ? 1u : 0u;
            }
            c1 = __reduce_add_sync(0xffffffffu, c1);
            c2 = __reduce_add_sync(0xffffffffu, c2);
            c3 = __reduce_add_sync(0xffffffffu, c3);
            if (lane == 0) {
                if (c1) atomicAdd(&cnt[r * 3 + 0], c1);
                if (c2) atomicAdd(&cnt[r * 3 + 1], c2);
                if (c3) atomicAdd(&cnt[r * 3 + 2], c3);
            }
            __syncthreads();
            if (cnt[r * 3 + 2] < KNN)      T = t3;
            else if (cnt[r * 3 + 1] < KNN) T = t2;
            else if (cnt[r * 3 + 0] < KNN) T = t1;
        }
        {
            unsigned t1 = T + 1u;
            unsigned c1 = 0;
#pragma unroll
            for (int t = 0; t < 16; ++t) c1 += (kreg[t] < t1) ? 1u : 0u;
            c1 = __reduce_add_sync(0xffffffffu, c1);
            if (lane == 0 && c1) atomicAdd(&cnt[45], c1);
            __syncthreads();
            if (cnt[45] < KNN) T = t1;
        }
    }
    {
        unsigned c = 0;
#pragma unroll
        for (int t = 0; t < 16; ++t) c += (kreg[t] < T) ? 1u : 0u;
        c = __reduce_add_sync(0xffffffffu, c);
        if (lane == 0 && c) atomicAdd(&cnt[46], c);
        __syncthreads();
    }
    int need = KNN - (int)cnt[46];

    // --- Phase D1: strict-less patch sums ---
    {
        float sx = 0.f, sy = 0.f, sz = 0.f;
#pragma unroll
        for (int t = 0; t < 16; ++t) {
            int n = t * 1024 + tid;
            if (n < N && kreg[t] < T) {
                const float* cp = g_canvas + (b * NMAX + n) * 3;
                sx += cp[0]; sy += cp[1]; sz += cp[2];
            }
        }
#pragma unroll
        for (int o = 16; o; o >>= 1) {
            sx += __shfl_down_sync(0xffffffffu, sx, o);
            sy += __shfl_down_sync(0xffffffffu, sy, o);
            sz += __shfl_down_sync(0xffffffffu, sz, o);
        }
        if (lane == 0) { fred[wid][0] = sx; fred[wid][1] = sy; fred[wid][2] = sz; }
        __syncthreads();
        if (tid == 0) {
            float tx = 0.f, ty = 0.f, tz = 0.f;
#pragma unroll
            for (int w = 0; w < 32; ++w) { tx += fred[w][0]; ty += fred[w][1]; tz += fred[w][2]; }
            acc3[0] = tx; acc3[1] = ty; acc3[2] = tz;
        }
        __syncthreads();
    }

    // --- Phase D2: radix-4 tie-break (need-th smallest tied index) ---
    if (need > 0) {
        unsigned Tidx = 0;
        int r = 0;
#pragma unroll 1
        for (int bpos = 12; bpos >= 0; bpos -= 2, ++r) {
            unsigned t1 = Tidx + (1u << bpos), t2 = Tidx + (2u << bpos), t3 = Tidx + (3u << bpos);
            unsigned c1 = 0, c2 = 0, c3 = 0;
#pragma unroll
            for (int t = 0; t < 16; ++t) {
                unsigned n = (unsigned)(t * 1024 + tid);
                bool tied = (kreg[t] == T);
                c1 += (tied && n < t1) ? 1u : 0u;
                c2 += (tied && n < t2) ? 1u : 0u;
                c3 += (tied && n < t3) ? 1u : 0u;
            }
            c1 = __reduce_add_sync(0xffffffffu, c1);
            c2 = __reduce_add_sync(0xffffffffu, c2);
            c3 = __reduce_add_sync(0xffffffffu, c3);
            if (lane == 0) {
                if (c1) atomicAdd(&cnt[47 + r * 3 + 0], c1);
                if (c2) atomicAdd(&cnt[47 + r * 3 + 1], c2);
                if (c3) atomicAdd(&cnt[47 + r * 3 + 2], c3);
            }
            __syncthreads();
            if (cnt[47 + r * 3 + 2] < (unsigned)need)      Tidx = t3;
            else if (cnt[47 + r * 3 + 1] < (unsigned)need) Tidx = t2;
            else if (cnt[47 + r * 3 + 0] < (unsigned)need) Tidx = t1;
        }
        float sx = 0.f, sy = 0.f, sz = 0.f;
#pragma unroll
        for (int t = 0; t < 16; ++t) {
            unsigned n = (unsigned)(t * 1024 + tid);
            if (kreg[t] == T && n <= Tidx) {
                const float* cp = g_canvas + (b * NMAX + (int)n) * 3;
                sx += cp[0]; sy += cp[1]; sz += cp[2];
            }
        }
#pragma unroll
        for (int o = 16; o; o >>= 1) {
            sx += __shfl_down_sync(0xffffffffu, sx, o);
            sy += __shfl_down_sync(0xffffffffu, sy, o);
            sz += __shfl_down_sync(0xffffffffu, sz, o);
        }
        if (lane == 0) { fred[wid][0] = sx; fred[wid][1] = sy; fred[wid][2] = sz; }
        __syncthreads();
        if (tid == 0) {
            float tx = acc3[0], ty = acc3[1], tz = acc3[2];
#pragma unroll
            for (int w = 0; w < 32; ++w) { tx += fred[w][0]; ty += fred[w][1]; tz += fred[w][2]; }
            acc3[0] = tx; acc3[1] = ty; acc3[2] = tz;
        }
        __syncthreads();
    }

    if (tid == 0) {
        in_s[256] = cx; in_s[257] = cy; in_s[258] = cz;
        in_s[259] = acc3[0] * (1.f / KNN) - cx;
        in_s[260] = acc3[1] * (1.f / KNN) - cy;
        in_s[261] = acc3[2] * (1.f / KNN) - cz;
        g_smax[b] = 0u;
    }
    if (tid < 256) in_s[tid] = fdec(g_gmax[b * GDIM + tid]);
    if (tid < 128) hnew[tid] = g_h[b * HDIM + tid];   // old h staged
    __syncthreads();

    // --- Phase E: LSTM gates GEMV, group-parallel float4 ---
    // 8 groups x 128 threads; thread owns output quad j=4q..4q+3; rows strided by 8.
    {
        int g = tid >> 7;          // 0..7
        int q = tid & 127;         // 0..127
        const float4* wih4 = reinterpret_cast<const float4*>(wih);   // row stride 128 quads
        const float4* whh4 = reinterpret_cast<const float4*>(whh);
        float4 acc = make_float4(0.f, 0.f, 0.f, 0.f);
#pragma unroll 4
        for (int r = g; r < 262; r += 8) {
            float xv = in_s[r];
            float4 w = wih4[r * 128 + q];
            acc.x += xv * w.x; acc.y += xv * w.y; acc.z += xv * w.z; acc.w += xv * w.w;
        }
#pragma unroll 4
        for (int r = g; r < 128; r += 8) {
            float xv = hnew[r];
            float4 w = whh4[r * 128 + q];
            acc.x += xv * w.x; acc.y += xv * w.y; acc.z += xv * w.z; acc.w += xv * w.w;
        }
        reinterpret_cast<float4*>(part)[g * 128 + q] = acc;
    }
    __syncthreads();
    if (tid < 512) {
        float s = bih[tid] + bhh[tid];
#pragma unroll
        for (int g = 0; g < 8; ++g) s += part[g * 512 + tid];
        gsm[tid] = s;
    }
    __syncthreads();
    if (tid < 128) {
        float gi = gsm[tid], gf = gsm[128 + tid], gg = gsm[256 + tid], go = gsm[384 + tid];
        float cn = sigm(gf) * g_c[b * HDIM + tid] + sigm(gi) * tanhf(gg);
        g_c[b * HDIM + tid] = cn;
        float hv = sigm(go) * tanhf(cn);
        g_h[b * HDIM + tid] = hv;
        hid[tid] = hv;   // h_new staged
    }
    __syncthreads();

    // --- Phase F: refine layer 1 GEMV (128->128), 16 groups x 32 threads ---
    if (tid < 512) {
        int g = tid >> 5;          // 0..15
        int q = tid & 31;          // output quad j=4q..4q+3
        const float4* rw14 = reinterpret_cast<const float4*>(rw1);   // row stride 32 quads
        float4 acc = make_float4(0.f, 0.f, 0.f, 0.f);
#pragma unroll
        for (int r = g; r < 128; r += 16) {   // 8 rows
            float xv = hid[r];
            float4 w = rw14[r * 32 + q];
            acc.x += xv * w.x; acc.y += xv * w.y; acc.z += xv * w.z; acc.w += xv * w.w;
        }
        reinterpret_cast<float4*>(part)[g * 32 + q] = acc;
    }
    __syncthreads();
    if (tid < 128) {
        float s = rb1[tid];
#pragma unroll
        for (int g = 0; g < 16; ++g) s += part[g * 128 + tid];
        hnew[tid] = fmaxf(s, 0.f);   // hidden layer
    }
    __syncthreads();

    // --- Phase G: refine layer 2 (128->3456), float4 outputs, 864 threads ---
    if (tid < 864) {
        const float4* rw24 = reinterpret_cast<const float4*>(rw2);   // row stride 864 quads
        const float4* rb24 = reinterpret_cast<const float4*>(rb2);
        float4 acc = rb24[tid];
#pragma unroll 8
        for (int k = 0; k < 128; ++k) {
            float hv = hnew[k];
            float4 w = rw24[k * 864 + tid];
            acc.x += hv * w.x; acc.y += hv * w.y; acc.z += hv * w.z; acc.w += hv * w.w;
        }
        float vals[4] = { acc.x, acc.y, acc.z, acc.w };
        int obase = 4 * tid;
#pragma unroll
        for (int u = 0; u < 4; ++u) {
            int o = obase + u;
            int p = o / 3, d = o - p * 3;
            float ctr = (d == 0) ? cx : (d == 1) ? cy : cz;
            g_canvas[(b * NMAX + N + p) * 3 + d] = vals[u] * 0.02f + ctr;
        }
    }
}

// ---------------- chamfer: 4 directions in one launch + fused final reduction ----------------
__global__ __launch_bounds__(256) void k_chamfer(const float* __restrict__ gt, float* __restrict__ out)
{
    int slot = blockIdx.z;
    int b = blockIdx.y;
    int tid = threadIdx.x;
    int totalBlocks = gridDim.x * gridDim.y * gridDim.z;
    __shared__ int chLast;

    const float* canvas_b = g_canvas + (size_t)b * NMAX * 3;
    const float* gt_b = gt + (size_t)b * N0 * 3;
    const float* X; const float* Y; int Nx, Ny;
    if (slot == 0)      { X = canvas_b;            Y = gt_b;              Nx = N0;   Ny = N0;   }
    else if (slot == 1) { X = gt_b;                Y = canvas_b;          Nx = N0;   Ny = N0;   }
    else if (slot == 2) { X = canvas_b + N0 * 3;   Y = gt_b;              Nx = NEWT; Ny = N0;   }
    else                { X = gt_b;                Y = canvas_b + N0 * 3; Nx = N0;   Ny = NEWT; }

    bool doWork = (blockIdx.x * 512 < Nx);
    if (doWork) {
        int i0 = blockIdx.x * 512 + tid;
        int i1 = i0 + 256;

        __shared__ float4 ys[256];

        bool v0 = i0 < Nx, v1 = i1 < Nx;
        float a0 = 0.f, a1 = 0.f, a2 = 0.f;
        float b0 = 0.f, b1v = 0.f, b2v = 0.f;
        if (v0) { const float* xp = X + (size_t)i0 * 3; a0 = xp[0]; a1 = xp[1]; a2 = xp[2]; }
        if (v1) { const float* xp = X + (size_t)i1 * 3; b0 = xp[0]; b1v = xp[1]; b2v = xp[2]; }

        float amin0 = 3.4e38f, amin1 = 3.4e38f;
        float bmin0 = 3.4e38f, bmin1 = 3.4e38f;
        for (int m0 = 0; m0 < Ny; m0 += 256) {
            __syncthreads();
            {
                const float* yp = Y + (size_t)(m0 + tid) * 3;
                float y0 = yp[0], y1 = yp[1], y2 = yp[2];
                ys[tid] = make_float4(-2.f * y0, -2.f * y1, -2.f * y2, y0 * y0 + y1 * y1 + y2 * y2);
            }
            __syncthreads();
#pragma unroll 4
            for (int t = 0; t < 256; t += 2) {
                float4 q0 = ys[t];
                float4 q1 = ys[t + 1];
                float da0 = q0.w + a0 * q0.x + a1 * q0.y + a2 * q0.z;
                float da1 = q1.w + a0 * q1.x + a1 * q1.y + a2 * q1.z;
                float db0 = q0.w + b0 * q0.x + b1v * q0.y + b2v * q0.z;
                float db1 = q1.w + b0 * q1.x + b1v * q1.y + b2v * q1.z;
                amin0 = fminf(amin0, da0);
                amin1 = fminf(amin1, da1);
                bmin0 = fminf(bmin0, db0);
                bmin1 = fminf(bmin1, db1);
            }
        }
        float ra = v0 ? (fminf(amin0, amin1) + a0 * a0 + a1 * a1 + a2 * a2) : 0.f;
        float rb = v1 ? (fminf(bmin0, bmin1) + b0 * b0 + b1v * b1v + b2v * b2v) : 0.f;

        float v = ra + rb;
#pragma unroll
        for (int o = 16; o; o >>= 1) v += __shfl_down_sync(0xffffffffu, v, o);
        __shared__ float wsum[8];
        if ((tid & 31) == 0) wsum[tid >> 5] = v;
        __syncthreads();
        if (tid == 0) {
            float s = 0.f;
#pragma unroll
            for (int w = 0; w < 8; ++w) s += wsum[w];
            atomicAdd(&g_closs[slot], s);
        }
    }

    __threadfence();
    __syncthreads();
    if (tid == 0) {
        int c = atomicAdd(&g_chCnt, 1);
        chLast = (c == totalBlocks - 1);
    }
    __syncthreads();
    if (chLast && tid == 0) {
        out[0] = 0.1f * (g_closs[0] * (1.f / (B * (float)N0)) + g_closs[1] * (1.f / (B * (float)N0)))
               + (g_closs[2] * (1.f / (B * (float)NEWT)) + g_closs[3] * (1.f / (B * (float)N0)));
        g_closs[0] = 0.f; g_closs[1] = 0.f; g_closs[2] = 0.f; g_closs[3] = 0.f;
        g_chCnt = 0;
    }
}

// ---------------- host ----------------
extern "C" void kernel_launch(void* const* d_in, const int* in_sizes, int n_in,
                              void* d_out, int out_size)
{
    const float* points   = (const float*)d_in[0];
    const float* gt       = (const float*)d_in[1];
    const float* enc_w1   = (const float*)d_in[2];
    const float* enc_b1   = (const float*)d_in[3];
    const float* enc_w2   = (const float*)d_in[4];
    const float* enc_b2   = (const float*)d_in[5];
    const float* enc_w3   = (const float*)d_in[6];
    const float* enc_b3   = (const float*)d_in[7];
    const float* att_w1   = (const float*)d_in[8];
    const float* att_b1   = (const float*)d_in[9];
    const float* att_w2   = (const float*)d_in[10];
    const float* att_b2   = (const float*)d_in[11];
    const float* lstm_wih = (const float*)d_in[12];
    const float* lstm_whh = (const float*)d_in[13];
    const float* lstm_bih = (const float*)d_in[14];
    const float* lstm_bhh = (const float*)d_in[15];
    const float* ref_w1   = (const float*)d_in[16];
    const float* ref_b1   = (const float*)d_in[17];
    const float* ref_w2   = (const float*)d_in[18];
    const float* ref_b2   = (const float*)d_in[19];
    float* out = (float*)d_out;

    k_init<<<(B * N0 * 3 + 255) / 256, 256>>>(points);

    for (int s = 0; s < STEPS; ++s) {
        int N = N0 + s * NEWP;
        int encFrom = (s == 0) ? 0 : (N - NEWP);
        int nNew = N - encFrom;  // 4096 or 1152, both divisible by 32
        dim3 ge(nNew / 32, B);
        k_enc<<<ge, 256>>>(enc_w1, enc_b1, enc_w2, enc_b2, enc_w3, enc_b3,
                           att_w1, att_b1, encFrom);
        dim3 gs((N + 127) / 128, B);
        k_scores<<<gs, 128>>>(att_w1, att_w2, att_b2, N);
        k_step<<<B, 1024>>>(lstm_wih, lstm_whh, lstm_bih, lstm_bhh,
                            ref_w1, ref_b1, ref_w2, ref_b2, N);
    }

    dim3 gc((NEWT + 511) / 512, B, 4);
    k_chamfer<<<gc, 256>>>(gt, out);
}